// round 4
// baseline (speedup 1.0000x reference)
#include <cuda_runtime.h>

// out[b,c] = dot(x[b,c,:HW], weight[c,:HW]) + bias[c]
// B = 512, C = 512, HW = 784 (float32). x is 822 MB streamed once.
// R4: kill the 822 MB weight L2 stream (R1 was LTS-cap bound, not HBM bound).
// Block tile = 32 b x 8 c; weight rows staged in smem (25 KB), reused 32x.

#define B_DIM 512
#define C_DIM 512
#define HW_DIM 784
#define HW_VEC4 (HW_DIM / 4)   // 196 float4 per row = 6*32 + 4

#define TILE_B 32
#define TILE_C 8
#define W_SMEM_FLOATS (TILE_C * HW_DIM)   // 6272 floats = 25088 B

__global__ __launch_bounds__(256) void scalar_mapping_kernel(
    const float* __restrict__ x,
    const float* __restrict__ weight,
    const float* __restrict__ bias,
    float* __restrict__ out)
{
    __shared__ float w_s[W_SMEM_FLOATS];
    __shared__ float bias_s[TILE_C];

    const int lane = threadIdx.x & 31;
    const int wid  = threadIdx.x >> 5;       // 0..7

    // Grid: 1024 blocks = 16 b-groups x 64 c-groups (c-group minor so the
    // concurrent wave covers contiguous c for the same b range).
    const int bg = blockIdx.x >> 6;           // 0..15
    const int cg = blockIdx.x & 63;           // 0..63
    const int b0 = bg * TILE_B;
    const int c0 = cg * TILE_C;

    // ---- Stage 8 weight rows (contiguous 25088 B) + bias into smem ----
    {
        const float* wsrc = weight + (size_t)c0 * HW_DIM;
        for (int i = threadIdx.x; i < W_SMEM_FLOATS; i += 256)
            w_s[i] = __ldg(&wsrc[i]);
        if (threadIdx.x < TILE_C)
            bias_s[threadIdx.x] = __ldg(&bias[c0 + threadIdx.x]);
    }
    __syncthreads();

    // ---- Each warp: 4 b's x 8 c's = 32 rows; per b the 8 rows are
    //      consecutive in memory (25 KB contiguous stream). ----
    #pragma unroll 1
    for (int bb = 0; bb < 4; ++bb) {
        const int b = b0 + wid * 4 + bb;

        #pragma unroll 1
        for (int j = 0; j < TILE_C; ++j) {
            const int row = b * C_DIM + c0 + j;
            const float4* __restrict__ xr =
                reinterpret_cast<const float4*>(x + (size_t)row * HW_DIM);
            const float4* __restrict__ wr =
                reinterpret_cast<const float4*>(w_s + j * HW_DIM);

            float s = 0.0f;
            #pragma unroll
            for (int i = 0; i < 7; ++i) {
                const int idx = lane + i * 32;
                if (idx < HW_VEC4) {
                    const float4 xv = __ldcs(&xr[idx]);  // DRAM stream, evict-first
                    const float4 wv = wr[idx];           // smem, conflict-free
                    s = fmaf(xv.x, wv.x, s);
                    s = fmaf(xv.y, wv.y, s);
                    s = fmaf(xv.z, wv.z, s);
                    s = fmaf(xv.w, wv.w, s);
                }
            }

            #pragma unroll
            for (int off = 16; off > 0; off >>= 1)
                s += __shfl_xor_sync(0xFFFFFFFFu, s, off);

            if (lane == 0)
                out[row] = s + bias_s[j];
        }
    }
}

extern "C" void kernel_launch(void* const* d_in, const int* in_sizes, int n_in,
                              void* d_out, int out_size)
{
    const float* x      = (const float*)d_in[0];
    const float* weight = (const float*)d_in[1];
    const float* bias   = (const float*)d_in[2];
    float* out          = (float*)d_out;

    // 256 rows per block -> 1024 blocks (single wave across 148 SMs).
    const int blocks = (B_DIM / TILE_B) * (C_DIM / TILE_C);  // 16 * 64 = 1024

    scalar_mapping_kernel<<<blocks, 256>>>(x, weight, bias, out);
}

// round 5
// speedup vs baseline: 1.2194x; 1.2194x over previous
#include <cuda_runtime.h>

// out[b,c] = dot(x[b,c,:HW], weight[c,:HW]) + bias[c]
// B = 512, C = 512, HW = 784 (float32). HBM-streaming bound: 822 MB of x read
// once. Measured path-independent memory ceiling on B300 is ~6300 B/cyc
// (~6.9 TB/s), and the R1 warp-per-row shape already runs at ~97% of it.
// R5 = R1 with 128-thread CTAs: finer block-churn granularity to shrink
// wave-synchronized lulls in the DRAM request stream. Per-warp code unchanged.

#define B_DIM 512
#define C_DIM 512
#define HW_DIM 784
#define HW_VEC4 (HW_DIM / 4)        // 196 float4 per row
#define TOTAL_ROWS (B_DIM * C_DIM)  // 262144

__global__ __launch_bounds__(128) void scalar_mapping_kernel(
    const float* __restrict__ x,
    const float* __restrict__ weight,
    const float* __restrict__ bias,
    float* __restrict__ out)
{
    const int warp = (blockIdx.x * blockDim.x + threadIdx.x) >> 5;  // row = b*C + c
    const int lane = threadIdx.x & 31;

    const int c = warp & (C_DIM - 1);

    const float4* __restrict__ xr =
        reinterpret_cast<const float4*>(x + (size_t)warp * HW_DIM);
    const float4* __restrict__ wr =
        reinterpret_cast<const float4*>(weight + (size_t)c * HW_DIM);

    float sum = 0.0f;

    // 196 float4 per row; 6 full warp-iterations + 1 partial (lanes 0-3).
    #pragma unroll
    for (int i = 0; i < 7; ++i) {
        const int idx = lane + i * 32;
        if (idx < HW_VEC4) {
            const float4 xv = __ldcs(&xr[idx]);  // x streamed once, evict-first
            const float4 wv = __ldg(&wr[idx]);   // weight stays L2-resident
            sum = fmaf(xv.x, wv.x, sum);
            sum = fmaf(xv.y, wv.y, sum);
            sum = fmaf(xv.z, wv.z, sum);
            sum = fmaf(xv.w, wv.w, sum);
        }
    }

    // Warp butterfly reduce
    #pragma unroll
    for (int off = 16; off > 0; off >>= 1)
        sum += __shfl_xor_sync(0xFFFFFFFFu, sum, off);

    if (lane == 0)
        out[warp] = sum + __ldg(&bias[c]);
}

extern "C" void kernel_launch(void* const* d_in, const int* in_sizes, int n_in,
                              void* d_out, int out_size)
{
    const float* x      = (const float*)d_in[0];
    const float* weight = (const float*)d_in[1];
    const float* bias   = (const float*)d_in[2];
    float* out          = (float*)d_out;

    // One warp per row; 4 warps per 128-thread block -> 65536 blocks in row
    // order (sequential DRAM window across the resident wave, fine-grained
    // churn so block retirement doesn't create synchronized DRAM lulls).
    const int blocks = TOTAL_ROWS / 4;

    scalar_mapping_kernel<<<blocks, 128>>>(x, weight, bias, out);
}

// round 6
// speedup vs baseline: 1.2414x; 1.0180x over previous
#include <cuda_runtime.h>

// out[b,c] = dot(x[b,c,:HW], weight[c,:HW]) + bias[c]
// B = 512, C = 512, HW = 784 (float32). HBM-streaming bound: 828 MB total DRAM
// traffic (x once + out), already minimal. R5 (128-thr CTAs) hit 85% DRAM /
// 6.74 TB/s. R6 continues the validated granularity axis: 64-thread CTAs
// (2 warps), halving the block retirement quantum again. Per-warp code
// unchanged from the winning shape.

#define B_DIM 512
#define C_DIM 512
#define HW_DIM 784
#define HW_VEC4 (HW_DIM / 4)        // 196 float4 per row
#define TOTAL_ROWS (B_DIM * C_DIM)  // 262144

__global__ __launch_bounds__(64) void scalar_mapping_kernel(
    const float* __restrict__ x,
    const float* __restrict__ weight,
    const float* __restrict__ bias,
    float* __restrict__ out)
{
    const int warp = (blockIdx.x * blockDim.x + threadIdx.x) >> 5;  // row = b*C + c
    const int lane = threadIdx.x & 31;

    const int c = warp & (C_DIM - 1);

    const float4* __restrict__ xr =
        reinterpret_cast<const float4*>(x + (size_t)warp * HW_DIM);
    const float4* __restrict__ wr =
        reinterpret_cast<const float4*>(weight + (size_t)c * HW_DIM);

    float sum = 0.0f;

    // 196 float4 per row; 6 full warp-iterations + 1 partial (lanes 0-3).
    #pragma unroll
    for (int i = 0; i < 7; ++i) {
        const int idx = lane + i * 32;
        if (idx < HW_VEC4) {
            const float4 xv = __ldcs(&xr[idx]);  // x streamed once, evict-first
            const float4 wv = __ldg(&wr[idx]);   // weight stays L2-resident
            sum = fmaf(xv.x, wv.x, sum);
            sum = fmaf(xv.y, wv.y, sum);
            sum = fmaf(xv.z, wv.z, sum);
            sum = fmaf(xv.w, wv.w, sum);
        }
    }

    // Warp butterfly reduce
    #pragma unroll
    for (int off = 16; off > 0; off >>= 1)
        sum += __shfl_xor_sync(0xFFFFFFFFu, sum, off);

    if (lane == 0)
        out[warp] = sum + __ldg(&bias[c]);
}

extern "C" void kernel_launch(void* const* d_in, const int* in_sizes, int n_in,
                              void* d_out, int out_size)
{
    const float* x      = (const float*)d_in[0];
    const float* weight = (const float*)d_in[1];
    const float* bias   = (const float*)d_in[2];
    float* out          = (float*)d_out;

    // One warp per row; 2 warps per 64-thread block -> 131072 blocks in row
    // order (sequential DRAM window, finest practical retirement granularity).
    const int blocks = TOTAL_ROWS / 2;

    scalar_mapping_kernel<<<blocks, 64>>>(x, weight, bias, out);
}